// round 14
// baseline (speedup 1.0000x reference)
#include <cuda_runtime.h>
#include <math.h>

#define BATCH 32
#define NTOK  4096
#define NSLOT 8
#define DIM   512
#define CH    32
#define CTOK  128
#define GTOK  16
#define ROWS  256

typedef unsigned long long u64;

// ---------------- packed f32x2 helpers ----------------
__device__ __forceinline__ u64 pk2(float lo, float hi) {
    u64 r; asm("mov.b64 %0, {%1, %2};" : "=l"(r) : "f"(lo), "f"(hi)); return r;
}
__device__ __forceinline__ void upk2(u64 v, float& a, float& b) {
    asm("mov.b64 {%0, %1}, %2;" : "=f"(a), "=f"(b) : "l"(v));
}
__device__ __forceinline__ u64 fma2_(u64 a, u64 b, u64 c) {
    u64 d; asm("fma.rn.f32x2 %0, %1, %2, %3;" : "=l"(d) : "l"(a), "l"(b), "l"(c)); return d;
}
__device__ __forceinline__ u64 add2_(u64 a, u64 b) {
    u64 d; asm("add.rn.f32x2 %0, %1, %2;" : "=l"(d) : "l"(a), "l"(b)); return d;
}
__device__ __forceinline__ u64 mul2_(u64 a, u64 b) {
    u64 d; asm("mul.rn.f32x2 %0, %1, %2;" : "=l"(d) : "l"(a), "l"(b)); return d;
}

// ---------------- device scratch ----------------
__device__ float g_qk   [4*ROWS*DIM];
__device__ float g_qb   [ROWS];
__device__ float g_Mqk  [2*DIM*DIM];
__device__ float g_rqk  [DIM];
__device__ float g_u    [DIM];
__device__ float g_c0   [1];
__device__ float g_scp  [8];
__device__ float g_upart[BATCH*CH*NSLOT*DIM];
__device__ float g_spart[BATCH*CH*NSLOT];
__device__ float g_upre [ROWS*DIM];
__device__ float g_upd  [2*ROWS*DIM];
__device__ float g_gx   [2*ROWS*3*DIM];
__device__ float g_gh   [2*ROWS*3*DIM];
__device__ float g_h1   [2*ROWS*DIM];

// ---------------- slot init ----------------
__global__ void init_slots_kernel(const float* __restrict__ noise,
                                  const float* __restrict__ mu,
                                  const float* __restrict__ sg,
                                  float* __restrict__ slots)
{
    int idx = blockIdx.x * blockDim.x + threadIdx.x;
    if (idx >= ROWS*DIM) return;
    int c = idx & (DIM-1);
    slots[idx] = mu[c] + fabsf(sg[c]) * noise[idx];
}

// ---------------- merged one-time prologue (grid 9, 128 thr) ----------------
__global__ void prologue_kernel(const float* __restrict__ Wq, const float* __restrict__ Wk,
                                const float* __restrict__ bq, const float* __restrict__ bk,
                                const float* __restrict__ gsl, const float* __restrict__ besl,
                                float* __restrict__ rqk, float* __restrict__ uvec,
                                float* __restrict__ scp, float* __restrict__ c0)
{
    int bid = blockIdx.x;
    int tid = threadIdx.x;
    if (bid < 4) {
        int f = bid*128 + tid;
        float acc = 0.f;
#pragma unroll 8
        for (int d = 0; d < DIM; d++) acc += __ldg(&bq[d]) * Wk[(size_t)d*DIM + f];
        rqk[f] = acc;
    } else if (bid < 8) {
        __shared__ float r1[128], r2[128];
        int e = (bid-4)*128 + tid;
        float acc = 0.f;
#pragma unroll 8
        for (int d = 0; d < DIM; d++) acc += __ldg(&bk[d]) * Wq[(size_t)d*DIM + e];
        uvec[e] = acc;
        r1[tid] = gsl[e]*acc;
        r2[tid] = besl[e]*acc;
        __syncthreads();
        for (int s = 64; s > 0; s >>= 1) {
            if (tid < s) { r1[tid] += r1[tid+s]; r2[tid] += r2[tid+s]; }
            __syncthreads();
        }
        if (tid == 0) { scp[2*(bid-4)+0] = r1[0]; scp[2*(bid-4)+1] = r2[0]; }
    } else {
        __shared__ float red[128];
        float acc = 0.f;
        for (int d = tid; d < DIM; d += 128) acc += bq[d]*bk[d];
        red[tid] = acc; __syncthreads();
        for (int s = 64; s > 0; s >>= 1) { if (tid < s) red[tid] += red[tid+s]; __syncthreads(); }
        if (tid == 0) *c0 = red[0];
    }
}

// ---------------- GRU elementwise (flat, sums split-K gate partials) ----------------
__global__ void gru_kernel(const float* __restrict__ gx, const float* __restrict__ gh,
                           float* __restrict__ slots)
{
    int t = blockIdx.x*256 + threadIdx.x;   // ROWS*DIM/4 = 32768 threads
    int row = t >> 7;
    int c = (t & 127) * 4;
    const float* gxm = gx + (size_t)row*3*DIM;
    const float* ghm = gh + (size_t)row*3*DIM;
    const size_t PO = (size_t)ROWS*3*DIM;
    float4 xr = *(const float4*)&gxm[c];
    float4 xz = *(const float4*)&gxm[DIM + c];
    float4 xn = *(const float4*)&gxm[2*DIM + c];
    float4 hr = *(const float4*)&ghm[c];
    float4 hz = *(const float4*)&ghm[DIM + c];
    float4 hn = *(const float4*)&ghm[2*DIM + c];
    float4 t4;
    t4 = *(const float4*)&gxm[PO + c];         xr.x+=t4.x; xr.y+=t4.y; xr.z+=t4.z; xr.w+=t4.w;
    t4 = *(const float4*)&gxm[PO + DIM + c];   xz.x+=t4.x; xz.y+=t4.y; xz.z+=t4.z; xz.w+=t4.w;
    t4 = *(const float4*)&gxm[PO + 2*DIM + c]; xn.x+=t4.x; xn.y+=t4.y; xn.z+=t4.z; xn.w+=t4.w;
    t4 = *(const float4*)&ghm[PO + c];         hr.x+=t4.x; hr.y+=t4.y; hr.z+=t4.z; hr.w+=t4.w;
    t4 = *(const float4*)&ghm[PO + DIM + c];   hz.x+=t4.x; hz.y+=t4.y; hz.z+=t4.z; hz.w+=t4.w;
    t4 = *(const float4*)&ghm[PO + 2*DIM + c]; hn.x+=t4.x; hn.y+=t4.y; hn.z+=t4.z; hn.w+=t4.w;
    float4 h4 = *(const float4*)&slots[(size_t)row*DIM + c];
    float4 o;
    {
        float r = 1.f/(1.f + __expf(-(xr.x + hr.x)));
        float z = 1.f/(1.f + __expf(-(xz.x + hz.x)));
        float n = tanhf(xn.x + r*hn.x);
        o.x = (1.f - z)*n + z*h4.x;
    }
    {
        float r = 1.f/(1.f + __expf(-(xr.y + hr.y)));
        float z = 1.f/(1.f + __expf(-(xz.y + hz.y)));
        float n = tanhf(xn.y + r*hn.y);
        o.y = (1.f - z)*n + z*h4.y;
    }
    {
        float r = 1.f/(1.f + __expf(-(xr.z + hr.z)));
        float z = 1.f/(1.f + __expf(-(xz.z + hz.z)));
        float n = tanhf(xn.z + r*hn.z);
        o.z = (1.f - z)*n + z*h4.z;
    }
    {
        float r = 1.f/(1.f + __expf(-(xr.w + hr.w)));
        float z = 1.f/(1.f + __expf(-(xz.w + hz.w)));
        float n = tanhf(xn.w + r*hn.w);
        o.w = (1.f - z)*n + z*h4.w;
    }
    *(float4*)&slots[(size_t)row*DIM + c] = o;
}

// ---------------- small GEMM: split-K, f32x2 mainloop, inline LN stats ----------------
#define GBM 16
#define GBN 64
#define GBK 32
#define GBM2 18
#define GBN2 68

struct GPtrs {
    const float* A; const float* A2; const float* B; const float* B2;
    const float* bias; const float* res;
    float* C; int cstride;
    const float* lng; const float* lnb;            // LN gamma/beta (full vectors)
    const float* uvec; const float* scp; const float* c0; float* qb;
};

template<bool TRANSA, bool TRANSB, bool RESID, bool LNA, int KS, bool RELUA, bool QBF>
__global__ __launch_bounds__(128) void gemm16(
    GPtrs p0, GPtrs p1, int lda, int ldb, int ldc, int K)
{
    __shared__ __align__(16) u64   As2[2][GBK*GBM2];
    __shared__ __align__(16) float Bs [2][GBK*GBN2];
    __shared__ float s_m[GBM], s_r[GBM];

    int khalf = blockIdx.z % KS;
    int pair  = blockIdx.z / KS;
    GPtrs P = (pair == 0) ? p0 : p1;
    int Keff = K / KS;

    const float* __restrict__ A0 = P.A;   // unsplit base (for stats)
    const float* __restrict__ A  = P.A;
    const float* __restrict__ A2 = P.A2;
    const float* __restrict__ B  = P.B;
    const float* __restrict__ B2v = P.B2;
    const float* __restrict__ lngo = P.lng;
    const float* __restrict__ lnbo = P.lnb;
    if (KS > 1) {
        if (TRANSA) A += (size_t)khalf * Keff * lda;
        else        A += khalf * Keff;
        if (A2) A2 += khalf * Keff;
        if (TRANSB) { B += khalf * Keff; if (B2v) B2v += khalf * Keff; }
        else        { B += (size_t)khalf * Keff * ldb; if (B2v) B2v += (size_t)khalf * Keff * ldb; }
        if (LNA) { lngo += khalf * Keff; lnbo += khalf * Keff; }
    }
    float* C = P.C + (size_t)khalf * P.cstride;

    int tid = threadIdx.x;
    int m0 = blockIdx.x * GBM;
    int n0 = blockIdx.y * GBN;
    int tx = tid & 15;
    int ty = tid >> 4;

    int a_m, a_k;
    if (TRANSA) { a_k = tid >> 2; a_m = (tid & 3) * 4; }
    else        { a_m = tid >> 3; a_k = (tid & 7) * 4; }

    // ---- inline LN row stats for the 16 A rows ----
    if (LNA) {
        int r  = tid >> 3;          // 0..15
        int cg = (tid & 7) * 64;
        const float* xr = &A0[(size_t)(m0 + r)*lda + cg];
        float sum = 0.f, ssq = 0.f, dgu = 0.f;
#pragma unroll
        for (int i = 0; i < 16; i++) {
            float4 v = *(const float4*)&xr[i*4];
            sum += v.x + v.y + v.z + v.w;
            ssq += v.x*v.x + v.y*v.y + v.z*v.z + v.w*v.w;
            if (QBF) {
                float4 g = *(const float4*)&P.lng[cg + i*4];
                float4 u = *(const float4*)&P.uvec[cg + i*4];
                dgu += v.x*g.x*u.x + v.y*g.y*u.y + v.z*g.z*u.z + v.w*g.w*u.w;
            }
        }
#pragma unroll
        for (int off = 4; off > 0; off >>= 1) {
            sum += __shfl_xor_sync(0xffffffffu, sum, off);
            ssq += __shfl_xor_sync(0xffffffffu, ssq, off);
            if (QBF) dgu += __shfl_xor_sync(0xffffffffu, dgu, off);
        }
        if ((tid & 7) == 0) {
            float mean = sum * (1.f/DIM);
            float var  = ssq * (1.f/DIM) - mean*mean;
            float rr   = rsqrtf(var + 1e-5f);
            s_m[r] = mean; s_r[r] = rr;
            if (QBF && n0 == 0 && khalf == 0 && pair == 0) {
                float S1 = P.scp[0] + P.scp[2] + P.scp[4] + P.scp[6];
                float S2 = P.scp[1] + P.scp[3] + P.scp[5] + P.scp[7] + *P.c0;
                P.qb[m0 + r] = rr*(dgu - mean*S1) + S2;
            }
        }
        __syncthreads();
    }
    float ln_m = 0.f, ln_r = 1.f;
    if (LNA) { ln_m = s_m[a_m]; ln_r = s_r[a_m]; }

    float4 ar;
    float4 br[4];

    u64 acc00 = 0ull, acc01 = 0ull, acc10 = 0ull, acc11 = 0ull;
    int nT = Keff / GBK;

    #define LOAD_A(t) do { \
        if (TRANSA) ar = *(const float4*)&A[(size_t)((t)*GBK + a_k)*lda + m0 + a_m]; \
        else        ar = *(const float4*)&A[(size_t)(m0 + a_m)*lda + (t)*GBK + a_k]; \
        if (!TRANSA && A2) { \
            float4 a2 = *(const float4*)&A2[(size_t)(m0 + a_m)*lda + (t)*GBK + a_k]; \
            ar.x += a2.x; ar.y += a2.y; ar.z += a2.z; ar.w += a2.w; \
        } \
        if (RELUA) { \
            ar.x = fmaxf(ar.x, 0.f); ar.y = fmaxf(ar.y, 0.f); \
            ar.z = fmaxf(ar.z, 0.f); ar.w = fmaxf(ar.w, 0.f); \
        } \
        if (LNA) { \
            float4 lg = *(const float4*)&lngo[(t)*GBK + a_k]; \
            float4 lb = *(const float4*)&lnbo[(t)*GBK + a_k]; \
            ar.x = (ar.x - ln_m)*ln_r*lg.x + lb.x; \
            ar.y = (ar.y - ln_m)*ln_r*lg.y + lb.y; \
            ar.z = (ar.z - ln_m)*ln_r*lg.z + lb.z; \
            ar.w = (ar.w - ln_m)*ln_r*lg.w + lb.w; \
        } \
    } while (0)
    #define LOAD_B(t) do { \
        _Pragma("unroll") \
        for (int it = 0; it < 4; it++) { \
            int idx = tid + it*128; \
            if (TRANSB) { int n = idx >> 3, kq = (idx & 7)*4; \
                br[it] = *(const float4*)&B[(size_t)(n0+n)*ldb + (t)*GBK + kq]; \
                if (B2v) { float4 e = *(const float4*)&B2v[(size_t)(n0+n)*ldb + (t)*GBK + kq]; \
                    br[it].x+=e.x; br[it].y+=e.y; br[it].z+=e.z; br[it].w+=e.w; } } \
            else { int kk = idx >> 4, nq = (idx & 15)*4; \
                br[it] = *(const float4*)&B[(size_t)((t)*GBK+kk)*ldb + n0 + nq]; \
                if (B2v) { float4 e = *(const float4*)&B2v[(size_t)((t)*GBK+kk)*ldb + n0 + nq]; \
                    br[it].x+=e.x; br[it].y+=e.y; br[it].z+=e.z; br[it].w+=e.w; } } \
        } \
    } while (0)
    #define STORE_AB(buf) do { \
        if (TRANSA) { \
            u64* dst = &As2[buf][a_k*GBM2 + a_m]; \
            dst[0] = pk2(ar.x, ar.x); dst[1] = pk2(ar.y, ar.y); \
            dst[2] = pk2(ar.z, ar.z); dst[3] = pk2(ar.w, ar.w); \
        } else { \
            As2[buf][(a_k+0)*GBM2 + a_m] = pk2(ar.x, ar.x); \
            As2[buf][(a_k+1)*GBM2 + a_m] = pk2(ar.y, ar.y); \
            As2[buf][(a_k+2)*GBM2 + a_m] = pk2(ar.z, ar.z); \
            As2[buf][(a_k+3)*GBM2 + a_m] = pk2(ar.w, ar.w); \
        } \
        _Pragma("unroll") \
        for (int it = 0; it < 4; it++) { \
            int idx = tid + it*128; \
            if (TRANSB) { int n = idx >> 3, kq = (idx & 7)*4; \
                Bs[buf][(kq+0)*GBN2 + n] = br[it].x; \
                Bs[buf][(kq+1)*GBN2 + n] = br[it].y; \
                Bs[buf][(kq+2)*GBN2 + n] = br[it].z; \
                Bs[buf][(kq+3)*GBN2 + n] = br[it].w; \
            } else { int kk = idx >> 4, nq = (idx & 15)*4; \
                *(float4*)&Bs[buf][kk*GBN2 + nq] = br[it]; } \
        } \
    } while (0)

    LOAD_A(0); LOAD_B(0);
    STORE_AB(0);
    __syncthreads();

    for (int t = 0; t < nT; t++) {
        int cur = t & 1;
        bool more = (t+1 < nT);
        if (more) { LOAD_A(t+1); LOAD_B(t+1); }
        ulonglong2 aa = *(const ulonglong2*)&As2[cur][0*GBM2 + ty*2];
        ulonglong2 bb = *(const ulonglong2*)&Bs [cur][0*GBN2 + tx*4];
#pragma unroll
        for (int kk = 0; kk < GBK; kk++) {
            ulonglong2 aan, bbn;
            if (kk + 1 < GBK) {
                aan = *(const ulonglong2*)&As2[cur][(kk+1)*GBM2 + ty*2];
                bbn = *(const ulonglong2*)&Bs [cur][(kk+1)*GBN2 + tx*4];
            }
            acc00 = fma2_(aa.x, bb.x, acc00);
            acc01 = fma2_(aa.x, bb.y, acc01);
            acc10 = fma2_(aa.y, bb.x, acc10);
            acc11 = fma2_(aa.y, bb.y, acc11);
            if (kk + 1 < GBK) { aa = aan; bb = bbn; }
        }
        if (more) {
            __syncthreads();
            STORE_AB((t+1) & 1);
            __syncthreads();
        }
    }
    #undef LOAD_A
    #undef LOAD_B
    #undef STORE_AB

    float c00a,c00b,c01a,c01b,c10a,c10b,c11a,c11b;
    upk2(acc00, c00a, c00b); upk2(acc01, c01a, c01b);
    upk2(acc10, c10a, c10b); upk2(acc11, c11a, c11b);

    float4 bv = make_float4(0.f,0.f,0.f,0.f);
    if (P.bias && khalf == 0) bv = *(const float4*)&P.bias[n0 + tx*4];

    float4 o0 = make_float4(c00a+bv.x, c00b+bv.y, c01a+bv.z, c01b+bv.w);
    float4 o1 = make_float4(c10a+bv.x, c10b+bv.y, c11a+bv.z, c11b+bv.w);
    size_t r0 = (size_t)(m0 + ty*2)*ldc + n0 + tx*4;
    size_t r1 = r0 + ldc;
    if (RESID && khalf == 0) {
        float4 q0 = *(const float4*)&P.res[r0];
        float4 q1 = *(const float4*)&P.res[r1];
        o0.x+=q0.x; o0.y+=q0.y; o0.z+=q0.z; o0.w+=q0.w;
        o1.x+=q1.x; o1.y+=q1.y; o1.z+=q1.z; o1.w+=q1.w;
    }
    *(float4*)&C[r0] = o0;
    *(float4*)&C[r1] = o1;
}

// ---------------- fused attention pass (software-pipelined loads) ----------------
#define ATTN_SMEM (NSLOT*DIM*4 + GTOK*DIM*4 + 2*DIM*4 + GTOK*NSLOT*8 + NSLOT*4 + NSLOT*NSLOT*4 + 64)

__global__ __launch_bounds__(256, 3) void attn_kernel2(
    const float* __restrict__ X,
    const float* __restrict__ g_in, const float* __restrict__ be_in,
    const float* __restrict__ QK, const float* __restrict__ QB,
    float* __restrict__ Upart, float* __restrict__ Spart)
{
    extern __shared__ __align__(16) char smraw[];
    float* qks = (float*)smraw;                       // [8][512]
    float* xs  = qks + NSLOT*DIM;                     // [16][512]
    float* gbs = xs + GTOK*DIM;                       // [2][512]
    u64*   psd = (u64*)(gbs + 2*DIM);                 // [16][8]
    float* qbs = (float*)(psd + GTOK*NSLOT);          // [8]
    float* sred= qbs + NSLOT;                         // [8][8]

    int b   = blockIdx.y;
    int ch  = blockIdx.x;
    int tid = threadIdx.x;
    int w = tid >> 5;
    int l = tid & 31;
    int cb4 = l * 4;

    // stage qk: sum 4 split-K planes
    for (int i = tid*4; i < NSLOT*DIM; i += 1024) {
        float4 a = *(const float4*)&QK[(size_t)b*NSLOT*DIM + i];
#pragma unroll
        for (int pl = 1; pl < 4; pl++) {
            float4 c = *(const float4*)&QK[(size_t)pl*ROWS*DIM + (size_t)b*NSLOT*DIM + i];
            a.x += c.x; a.y += c.y; a.z += c.z; a.w += c.w;
        }
        *(float4*)&qks[i] = a;
    }
    if (tid < 128) {
        *(float4*)&gbs[tid*4]       = *(const float4*)&g_in[tid*4];
        *(float4*)&gbs[DIM + tid*4] = *(const float4*)&be_in[tid*4];
    }
    if (tid < NSLOT) qbs[tid] = QB[b*NSLOT + tid];
    __syncthreads();

    u64 U2[8];
#pragma unroll
    for (int i = 0; i < 8; i++) U2[i] = 0ull;
    float slp = 0.f;

    const float scale = 0.04419417382415922f;   // 512^-0.5
    int tA = 2*w, tB = 2*w + 1;
    int xoff = w*64 + l*2;
    int myslot = (l >> 1) & 7;
    const float* xbase = X + ((size_t)b*NTOK + ch*CTOK)*DIM;

    u64 xvA[8], xvB[8];
    // preload group 0
    {
        const float* xrA = xbase + (size_t)tA*DIM;
        const float* xrB = xrA + DIM;
#pragma unroll
        for (int s = 0; s < 4; s++) {
            ulonglong2 a2 = *(const ulonglong2*)&xrA[s*128 + cb4];
            ulonglong2 b2 = *(const ulonglong2*)&xrB[s*128 + cb4];
            xvA[2*s] = a2.x; xvA[2*s+1] = a2.y;
            xvB[2*s] = b2.x; xvB[2*s+1] = b2.y;
        }
    }

    for (int g = 0; g < CTOK/GTOK; g++) {
        // ---- stats from current registers ----
        u64 sA2 = 0ull, qA2 = 0ull, sB2 = 0ull, qB2 = 0ull;
#pragma unroll
        for (int s = 0; s < 8; s++) {
            sA2 = add2_(sA2, xvA[s]); qA2 = fma2_(xvA[s], xvA[s], qA2);
            sB2 = add2_(sB2, xvB[s]); qB2 = fma2_(xvB[s], xvB[s], qB2);
        }
        float t0, t1;
        upk2(sA2, t0, t1); float sumA = t0 + t1;
        upk2(qA2, t0, t1); float ssqA = t0 + t1;
        upk2(sB2, t0, t1); float sumB = t0 + t1;
        upk2(qB2, t0, t1); float ssqB = t0 + t1;
#pragma unroll
        for (int off = 16; off > 0; off >>= 1) {
            sumA += __shfl_xor_sync(0xffffffffu, sumA, off);
            ssqA += __shfl_xor_sync(0xffffffffu, ssqA, off);
            sumB += __shfl_xor_sync(0xffffffffu, sumB, off);
            ssqB += __shfl_xor_sync(0xffffffffu, ssqB, off);
        }
        float meanA = sumA * (1.f/DIM);
        float invA  = rsqrtf(ssqA*(1.f/DIM) - meanA*meanA + 1e-5f);
        float meanB = sumB * (1.f/DIM);
        float invB  = rsqrtf(ssqB*(1.f/DIM) - meanB*meanB + 1e-5f);
        u64 invA2 = pk2(invA, invA), nmA2 = pk2(-meanA, -meanA);
        u64 invB2 = pk2(invB, invB), nmB2 = pk2(-meanB, -meanB);

        // ---- LN + dots (consumes xv registers) ----
        u64 dA2[8], dB2[8];
#pragma unroll
        for (int i = 0; i < 8; i++) { dA2[i] = 0ull; dB2[i] = 0ull; }
#pragma unroll
        for (int s = 0; s < 4; s++) {
            int c = s*128 + cb4;
            ulonglong2 g2 = *(const ulonglong2*)&gbs[c];
            ulonglong2 b2 = *(const ulonglong2*)&gbs[DIM + c];
            u64 giA0 = mul2_(g2.x, invA2), giA1 = mul2_(g2.y, invA2);
            u64 kA0  = fma2_(nmA2, giA0, b2.x), kA1 = fma2_(nmA2, giA1, b2.y);
            u64 xnA0 = fma2_(xvA[2*s],   giA0, kA0);
            u64 xnA1 = fma2_(xvA[2*s+1], giA1, kA1);
            *(ulonglong2*)&xs[tA*DIM + c] = make_ulonglong2(xnA0, xnA1);
            u64 giB0 = mul2_(g2.x, invB2), giB1 = mul2_(g2.y, invB2);
            u64 kB0  = fma2_(nmB2, giB0, b2.x), kB1 = fma2_(nmB2, giB1, b2.y);
            u64 xnB0 = fma2_(xvB[2*s],   giB0, kB0);
            u64 xnB1 = fma2_(xvB[2*s+1], giB1, kB1);
            *(ulonglong2*)&xs[tB*DIM + c] = make_ulonglong2(xnB0, xnB1);
#pragma unroll
            for (int i = 0; i < 8; i++) {
                ulonglong2 q2 = *(const ulonglong2*)&qks[i*DIM + c];
                dA2[i] = fma2_(q2.x, xnA0, dA2[i]);
                dA2[i] = fma2_(q2.y, xnA1, dA2[i]);
                dB2[i] = fma2_(q2.x, xnB0, dB2[i]);
                dB2[i] = fma2_(q2.y, xnB1, dB2[i]);
            }
        }

        // ---- prefetch next group's tokens (xv registers now dead) ----
        if (g + 1 < CTOK/GTOK) {
            const float* xrA = xbase + (size_t)((g+1)*GTOK + tA)*DIM;
            const float* xrB = xrA + DIM;
#pragma unroll
            for (int s = 0; s < 4; s++) {
                ulonglong2 a2 = *(const ulonglong2*)&xrA[s*128 + cb4];
                ulonglong2 b2 = *(const ulonglong2*)&xrB[s*128 + cb4];
                xvA[2*s] = a2.x; xvA[2*s+1] = a2.y;
                xvB[2*s] = b2.x; xvB[2*s+1] = b2.y;
            }
        }

        float vA[8], vB[8];
#pragma unroll
        for (int i = 0; i < 8; i++) {
            float a0, a1;
            upk2(dA2[i], a0, a1); vA[i] = a0 + a1;
            upk2(dB2[i], a0, a1); vB[i] = a0 + a1;
        }
        // ---- value-compressing butterfly reduce ----
        float v8[8];
#pragma unroll
        for (int i = 0; i < 8; i++) {
            float sa = vA[i] + __shfl_xor_sync(0xffffffffu, vA[i], 16);
            float sb = vB[i] + __shfl_xor_sync(0xffffffffu, vB[i], 16);
            v8[i] = (l < 16) ? sa : sb;
        }
        float v4[4];
#pragma unroll
        for (int i = 0; i < 4; i++) {
            float a = v8[i]   + __shfl_xor_sync(0xffffffffu, v8[i],   8);
            float c = v8[i+4] + __shfl_xor_sync(0xffffffffu, v8[i+4], 8);
            v4[i] = (l & 8) ? c : a;
        }
        float v2[2];
#pragma unroll
        for (int i = 0; i < 2; i++) {
            float a = v4[i]   + __shfl_xor_sync(0xffffffffu, v4[i],   4);
            float c = v4[i+2] + __shfl_xor_sync(0xffffffffu, v4[i+2], 4);
            v2[i] = (l & 4) ? c : a;
        }
        {
            float a = v2[0] + __shfl_xor_sync(0xffffffffu, v2[0], 2);
            float c = v2[1] + __shfl_xor_sync(0xffffffffu, v2[1], 2);
            v2[0] = (l & 2) ? c : a;
        }
        float d = v2[0] + __shfl_xor_sync(0xffffffffu, v2[0], 1);
        d = (d + qbs[myslot]) * scale;
        // distributed softmax over 8 slots within each 16-lane half
        float mx = d;
        mx = fmaxf(mx, __shfl_xor_sync(0xffffffffu, mx, 2));
        mx = fmaxf(mx, __shfl_xor_sync(0xffffffffu, mx, 4));
        mx = fmaxf(mx, __shfl_xor_sync(0xffffffffu, mx, 8));
        float e = __expf(d - mx);
        float se = e;
        se += __shfl_xor_sync(0xffffffffu, se, 2);
        se += __shfl_xor_sync(0xffffffffu, se, 4);
        se += __shfl_xor_sync(0xffffffffu, se, 8);
        float pcur = e / se + 1e-8f;
        slp += pcur;
        if ((l & 1) == 0) {
            int tok = (l < 16) ? tA : tB;
            psd[tok*NSLOT + myslot] = pk2(pcur, pcur);
        }
        __syncthreads();

        // ---- phase 2: warp w accumulates its 64-dim slice for all slots ----
#pragma unroll
        for (int t = 0; t < GTOK; t++) {
            u64 x2 = *(const u64*)&xs[t*DIM + xoff];
            ulonglong2 p01 = *(const ulonglong2*)&psd[t*NSLOT + 0];
            ulonglong2 p23 = *(const ulonglong2*)&psd[t*NSLOT + 2];
            ulonglong2 p45 = *(const ulonglong2*)&psd[t*NSLOT + 4];
            ulonglong2 p67 = *(const ulonglong2*)&psd[t*NSLOT + 6];
            U2[0] = fma2_(p01.x, x2, U2[0]); U2[1] = fma2_(p01.y, x2, U2[1]);
            U2[2] = fma2_(p23.x, x2, U2[2]); U2[3] = fma2_(p23.y, x2, U2[3]);
            U2[4] = fma2_(p45.x, x2, U2[4]); U2[5] = fma2_(p45.y, x2, U2[5]);
            U2[6] = fma2_(p67.x, x2, U2[6]); U2[7] = fma2_(p67.y, x2, U2[7]);
        }
        __syncthreads();
    }

    size_t ub = ((size_t)(b*CH + ch)*NSLOT)*DIM + xoff;
#pragma unroll
    for (int i = 0; i < 8; i++)
        *(u64*)&Upart[ub + (size_t)i*DIM] = U2[i];

    slp += __shfl_xor_sync(0xffffffffu, slp, 16);
    slp += __shfl_xor_sync(0xffffffffu, slp, 1);
    if ((l & 1) == 0 && l < 16) sred[w*8 + (l >> 1)] = slp * 0.5f;
    __syncthreads();
    if (tid < 8) {
        float s = 0.f;
#pragma unroll
        for (int w2 = 0; w2 < 8; w2++) s += sred[w2*8 + tid];
        Spart[(b*CH + ch)*NSLOT + tid] = s;
    }
}

// ---------------- reduce partials ----------------
__global__ void finish_kernel(const float* __restrict__ Upart,
                              const float* __restrict__ Spart,
                              float* __restrict__ Upre)
{
    int bi = blockIdx.x;
    int b = bi >> 3, i = bi & 7;
    int tid = threadIdx.x;          // 128
    __shared__ float ssum_s;
    if (tid < 32) {
        float s = Spart[(b*CH + tid)*NSLOT + i];
#pragma unroll
        for (int off = 16; off > 0; off >>= 1) s += __shfl_xor_sync(0xffffffffu, s, off);
        if (tid == 0) ssum_s = s;
    }
    __syncthreads();
    float rs = 1.f / ssum_s;
    int c = tid * 4;
    float4 acc = make_float4(0.f,0.f,0.f,0.f);
    for (int chn = 0; chn < CH; chn++) {
        float4 v = *(const float4*)&Upart[(((size_t)b*CH + chn)*NSLOT + i)*DIM + c];
        acc.x += v.x; acc.y += v.y; acc.z += v.z; acc.w += v.w;
    }
    acc.x*=rs; acc.y*=rs; acc.z*=rs; acc.w*=rs;
    *(float4*)&Upre[(size_t)bi*DIM + c] = acc;
}

// ---------------- host orchestration ----------------
extern "C" void kernel_launch(void* const* d_in, const int* in_sizes, int n_in,
                              void* d_out, int out_size)
{
    const float* inputs = (const float*)d_in[0];
    const float* noise  = (const float*)d_in[1];
    const float* mu     = (const float*)d_in[2];
    const float* sg     = (const float*)d_in[3];
    const float* Wq = (const float*)d_in[4];
    const float* bq = (const float*)d_in[5];
    const float* Wk = (const float*)d_in[6];
    const float* bk = (const float*)d_in[7];
    const float* Wv = (const float*)d_in[8];
    const float* bv = (const float*)d_in[9];
    const float* W_ih = (const float*)d_in[10];
    const float* b_ih = (const float*)d_in[11];
    const float* W_hh = (const float*)d_in[12];
    const float* b_hh = (const float*)d_in[13];
    const float* W1 = (const float*)d_in[14];
    const float* b1 = (const float*)d_in[15];
    const float* W2 = (const float*)d_in[16];
    const float* b2 = (const float*)d_in[17];
    const float* gin  = (const float*)d_in[18];
    const float* bein = (const float*)d_in[19];
    const float* gsl  = (const float*)d_in[20];
    const float* besl = (const float*)d_in[21];
    const float* gff  = (const float*)d_in[22];
    const float* beff = (const float*)d_in[23];

    float* slots = (float*)d_out;

    void* p;
    cudaGetSymbolAddress(&p, g_qk);    float* qk    = (float*)p;
    cudaGetSymbolAddress(&p, g_qb);    float* qb    = (float*)p;
    cudaGetSymbolAddress(&p, g_Mqk);   float* Mqk   = (float*)p;
    cudaGetSymbolAddress(&p, g_rqk);   float* rqk   = (float*)p;
    cudaGetSymbolAddress(&p, g_u);     float* uvec  = (float*)p;
    cudaGetSymbolAddress(&p, g_c0);    float* c0    = (float*)p;
    cudaGetSymbolAddress(&p, g_scp);   float* scp   = (float*)p;
    cudaGetSymbolAddress(&p, g_upart); float* upart = (float*)p;
    cudaGetSymbolAddress(&p, g_spart); float* spart = (float*)p;
    cudaGetSymbolAddress(&p, g_upre);  float* upre  = (float*)p;
    cudaGetSymbolAddress(&p, g_upd);   float* upd   = (float*)p;
    cudaGetSymbolAddress(&p, g_gx);    float* gx    = (float*)p;
    cudaGetSymbolAddress(&p, g_gh);    float* gh    = (float*)p;
    cudaGetSymbolAddress(&p, g_h1);    float* h1    = (float*)p;

    static bool attr_done = false;
    if (!attr_done) {
        cudaFuncSetAttribute(attn_kernel2, cudaFuncAttributeMaxDynamicSharedMemorySize, ATTN_SMEM);
        attr_done = true;
    }

    GPtrs Z{};

    init_slots_kernel<<<(ROWS*DIM + 255)/256, 256>>>(noise, mu, sg, slots);
    prologue_kernel<<<9, 128>>>(Wq, Wk, bq, bk, gsl, besl, rqk, uvec, scp, c0);

    // Mqk = Wq^T @ Wk (split-K=2, planes summed by qk-GEMM B-load)
    {
        GPtrs a = Z; a.A = Wq; a.B = Wk; a.C = Mqk; a.cstride = DIM*DIM;
        gemm16<true,false,false,false,2,false,false><<<dim3(DIM/GBM, DIM/GBN, 2), 128>>>(a, a, DIM, DIM, DIM, DIM);
    }

    for (int it = 0; it < 3; it++) {
        // qk = LN(slots) @ (Mqk0+Mqk1) + rqk ; inline row stats + qb (split-K=4)
        {
            GPtrs a = Z; a.A = slots; a.B = Mqk; a.B2 = Mqk + DIM*DIM; a.bias = rqk;
            a.C = qk; a.cstride = ROWS*DIM;
            a.lng = gsl; a.lnb = besl; a.uvec = uvec; a.scp = scp; a.c0 = c0; a.qb = qb;
            gemm16<false,false,false,true,4,false,true><<<dim3(ROWS/GBM, DIM/GBN, 4), 128>>>(a, a, DIM, DIM, DIM, DIM);
        }
        attn_kernel2<<<dim3(CH, BATCH), 256, ATTN_SMEM>>>(inputs, gin, bein, qk, qb, upart, spart);
        finish_kernel<<<ROWS, 128>>>(upart, spart, upre);
        // upd partials = Upre @ Wv^T + bv   (split-K=2)
        {
            GPtrs a = Z; a.A = upre; a.B = Wv; a.bias = bv; a.C = upd; a.cstride = ROWS*DIM;
            gemm16<false,true,false,false,2,false,false><<<dim3(ROWS/GBM, DIM/GBN, 2), 128>>>(a, a, DIM, DIM, DIM, DIM);
        }
        // GRU gates (pairs x split-K=2)
        {
            GPtrs a = Z; a.A = upd;   a.A2 = upd + ROWS*DIM; a.B = W_ih; a.bias = b_ih; a.C = gx; a.cstride = ROWS*3*DIM;
            GPtrs b = Z; b.A = slots; b.A2 = nullptr;        b.B = W_hh; b.bias = b_hh; b.C = gh; b.cstride = ROWS*3*DIM;
            gemm16<false,true,false,false,2,false,false><<<dim3(ROWS/GBM, (3*DIM)/GBN, 4), 128>>>(a, b, DIM, DIM, 3*DIM, DIM);
        }
        gru_kernel<<<ROWS*DIM/4/256, 256>>>(gx, gh, slots);
        // h1 = LN_ff(slots) @ W1^T + b1 ; inline row stats (split-K=2)
        {
            GPtrs a = Z; a.A = slots; a.B = W1; a.bias = b1; a.C = h1; a.cstride = ROWS*DIM;
            a.lng = gff; a.lnb = beff;
            gemm16<false,true,false,true,2,false,false><<<dim3(ROWS/GBM, DIM/GBN, 2), 128>>>(a, a, DIM, DIM, DIM, DIM);
        }
        // slots += relu(h10+h11) @ W2^T + b2
        {
            GPtrs a = Z; a.A = h1; a.A2 = h1 + ROWS*DIM; a.B = W2; a.bias = b2; a.res = slots; a.C = slots; a.cstride = 0;
            gemm16<false,true,true,false,1,true,false><<<dim3(ROWS/GBM, DIM/GBN, 1), 128>>>(a, a, DIM, DIM, DIM, DIM);
        }
    }
}

// round 15
// speedup vs baseline: 1.0257x; 1.0257x over previous
#include <cuda_runtime.h>
#include <math.h>

#define BATCH 32
#define NTOK  4096
#define NSLOT 8
#define DIM   512
#define CH    32
#define CTOK  128
#define GTOK  16
#define ROWS  256

typedef unsigned long long u64;

// ---------------- packed f32x2 helpers ----------------
__device__ __forceinline__ u64 pk2(float lo, float hi) {
    u64 r; asm("mov.b64 %0, {%1, %2};" : "=l"(r) : "f"(lo), "f"(hi)); return r;
}
__device__ __forceinline__ void upk2(u64 v, float& a, float& b) {
    asm("mov.b64 {%0, %1}, %2;" : "=f"(a), "=f"(b) : "l"(v));
}
__device__ __forceinline__ u64 fma2_(u64 a, u64 b, u64 c) {
    u64 d; asm("fma.rn.f32x2 %0, %1, %2, %3;" : "=l"(d) : "l"(a), "l"(b), "l"(c)); return d;
}
__device__ __forceinline__ u64 add2_(u64 a, u64 b) {
    u64 d; asm("add.rn.f32x2 %0, %1, %2;" : "=l"(d) : "l"(a), "l"(b)); return d;
}
__device__ __forceinline__ u64 mul2_(u64 a, u64 b) {
    u64 d; asm("mul.rn.f32x2 %0, %1, %2;" : "=l"(d) : "l"(a), "l"(b)); return d;
}

// ---------------- device scratch ----------------
__device__ float g_qk   [2*ROWS*DIM];
__device__ float g_qb   [ROWS];
__device__ float g_Mqk  [2*DIM*DIM];
__device__ float g_rqk  [DIM];
__device__ float g_u    [DIM];
__device__ float g_c0   [1];
__device__ float g_scp  [8];
__device__ float g_mq   [ROWS];
__device__ float g_rq   [ROWS];
__device__ float g_mf   [ROWS];
__device__ float g_rf   [ROWS];
__device__ float g_upart[BATCH*CH*NSLOT*DIM];
__device__ float g_spart[BATCH*CH*NSLOT];
__device__ float g_upre [ROWS*DIM];
__device__ float g_upd  [2*ROWS*DIM];
__device__ float g_gx   [2*ROWS*3*DIM];
__device__ float g_gh   [2*ROWS*3*DIM];
__device__ float g_h1   [2*ROWS*DIM];

// ---------------- slot init ----------------
__global__ void init_slots_kernel(const float* __restrict__ noise,
                                  const float* __restrict__ mu,
                                  const float* __restrict__ sg,
                                  float* __restrict__ slots)
{
    int idx = blockIdx.x * blockDim.x + threadIdx.x;
    if (idx >= ROWS*DIM) return;
    int c = idx & (DIM-1);
    slots[idx] = mu[c] + fabsf(sg[c]) * noise[idx];
}

// ---------------- merged one-time prologue (grid 9, 128 thr) ----------------
__global__ void prologue_kernel(const float* __restrict__ Wq, const float* __restrict__ Wk,
                                const float* __restrict__ bq, const float* __restrict__ bk,
                                const float* __restrict__ gsl, const float* __restrict__ besl,
                                float* __restrict__ rqk, float* __restrict__ uvec,
                                float* __restrict__ scp, float* __restrict__ c0)
{
    int bid = blockIdx.x;
    int tid = threadIdx.x;
    if (bid < 4) {
        int f = bid*128 + tid;
        float acc = 0.f;
#pragma unroll 8
        for (int d = 0; d < DIM; d++) acc += __ldg(&bq[d]) * Wk[(size_t)d*DIM + f];
        rqk[f] = acc;
    } else if (bid < 8) {
        __shared__ float r1[128], r2[128];
        int e = (bid-4)*128 + tid;
        float acc = 0.f;
#pragma unroll 8
        for (int d = 0; d < DIM; d++) acc += __ldg(&bk[d]) * Wq[(size_t)d*DIM + e];
        uvec[e] = acc;
        r1[tid] = gsl[e]*acc;
        r2[tid] = besl[e]*acc;
        __syncthreads();
        for (int s = 64; s > 0; s >>= 1) {
            if (tid < s) { r1[tid] += r1[tid+s]; r2[tid] += r2[tid+s]; }
            __syncthreads();
        }
        if (tid == 0) { scp[2*(bid-4)+0] = r1[0]; scp[2*(bid-4)+1] = r2[0]; }
    } else {
        __shared__ float red[128];
        float acc = 0.f;
        for (int d = tid; d < DIM; d += 128) acc += bq[d]*bk[d];
        red[tid] = acc; __syncthreads();
        for (int s = 64; s > 0; s >>= 1) { if (tid < s) red[tid] += red[tid+s]; __syncthreads(); }
        if (tid == 0) *c0 = red[0];
    }
}

// ---------------- per-row LN stats for q-path (+ fused qb) ----------------
__global__ void stats_q_kernel(const float* __restrict__ slots,
                               const float* __restrict__ gsl,
                               const float* __restrict__ uvec,
                               const float* __restrict__ scp,
                               const float* __restrict__ c0,
                               float* __restrict__ meanq, float* __restrict__ rstdq,
                               float* __restrict__ qb)
{
    int row = blockIdx.x * 8 + (threadIdx.x >> 5);
    int l   = threadIdx.x & 31;
    const float* x = slots + (size_t)row * DIM;
    float sum = 0.f, ssq = 0.f, dgu = 0.f;
#pragma unroll
    for (int s = 0; s < 4; s++) {
        int c = s*128 + l*4;
        float4 v  = *(const float4*)&x[c];
        float4 gv = *(const float4*)&gsl[c];
        float4 uv = *(const float4*)&uvec[c];
        sum += v.x + v.y + v.z + v.w;
        ssq += v.x*v.x + v.y*v.y + v.z*v.z + v.w*v.w;
        dgu += v.x*gv.x*uv.x + v.y*gv.y*uv.y + v.z*gv.z*uv.z + v.w*gv.w*uv.w;
    }
#pragma unroll
    for (int off = 16; off > 0; off >>= 1) {
        sum += __shfl_xor_sync(0xffffffffu, sum, off);
        ssq += __shfl_xor_sync(0xffffffffu, ssq, off);
        dgu += __shfl_xor_sync(0xffffffffu, dgu, off);
    }
    if (l == 0) {
        float S1 = scp[0] + scp[2] + scp[4] + scp[6];
        float S2 = scp[1] + scp[3] + scp[5] + scp[7] + *c0;
        float mean = sum * (1.f/DIM);
        float var  = ssq * (1.f/DIM) - mean*mean;
        float r    = rsqrtf(var + 1e-5f);
        meanq[row] = mean;
        rstdq[row] = r;
        qb[row]    = r*(dgu - mean*S1) + S2;
    }
}

// ---------------- GRU elementwise (sums split-K gate partials) + ff-LN stats ----------------
__global__ void gru_ln_kernel(const float* __restrict__ gx, const float* __restrict__ gh,
                              float* __restrict__ slots,
                              float* __restrict__ meanf, float* __restrict__ rstdf)
{
    __shared__ float r1[4], r2[4];
    int row = blockIdx.x;
    int tid = threadIdx.x;      // 128
    int c = tid * 4;
    const float* gxm = gx + (size_t)row*3*DIM;
    const float* ghm = gh + (size_t)row*3*DIM;
    const size_t PO = (size_t)ROWS*3*DIM;
    float4 xr = *(const float4*)&gxm[c];
    float4 xz = *(const float4*)&gxm[DIM + c];
    float4 xn = *(const float4*)&gxm[2*DIM + c];
    float4 hr = *(const float4*)&ghm[c];
    float4 hz = *(const float4*)&ghm[DIM + c];
    float4 hn = *(const float4*)&ghm[2*DIM + c];
    float4 t4;
    t4 = *(const float4*)&gxm[PO + c];         xr.x+=t4.x; xr.y+=t4.y; xr.z+=t4.z; xr.w+=t4.w;
    t4 = *(const float4*)&gxm[PO + DIM + c];   xz.x+=t4.x; xz.y+=t4.y; xz.z+=t4.z; xz.w+=t4.w;
    t4 = *(const float4*)&gxm[PO + 2*DIM + c]; xn.x+=t4.x; xn.y+=t4.y; xn.z+=t4.z; xn.w+=t4.w;
    t4 = *(const float4*)&ghm[PO + c];         hr.x+=t4.x; hr.y+=t4.y; hr.z+=t4.z; hr.w+=t4.w;
    t4 = *(const float4*)&ghm[PO + DIM + c];   hz.x+=t4.x; hz.y+=t4.y; hz.z+=t4.z; hz.w+=t4.w;
    t4 = *(const float4*)&ghm[PO + 2*DIM + c]; hn.x+=t4.x; hn.y+=t4.y; hn.z+=t4.z; hn.w+=t4.w;
    float4 h4 = *(const float4*)&slots[(size_t)row*DIM + c];
    float4 o;
    {
        float r = 1.f/(1.f + __expf(-(xr.x + hr.x)));
        float z = 1.f/(1.f + __expf(-(xz.x + hz.x)));
        float n = tanhf(xn.x + r*hn.x);
        o.x = (1.f - z)*n + z*h4.x;
    }
    {
        float r = 1.f/(1.f + __expf(-(xr.y + hr.y)));
        float z = 1.f/(1.f + __expf(-(xz.y + hz.y)));
        float n = tanhf(xn.y + r*hn.y);
        o.y = (1.f - z)*n + z*h4.y;
    }
    {
        float r = 1.f/(1.f + __expf(-(xr.z + hr.z)));
        float z = 1.f/(1.f + __expf(-(xz.z + hz.z)));
        float n = tanhf(xn.z + r*hn.z);
        o.z = (1.f - z)*n + z*h4.z;
    }
    {
        float r = 1.f/(1.f + __expf(-(xr.w + hr.w)));
        float z = 1.f/(1.f + __expf(-(xz.w + hz.w)));
        float n = tanhf(xn.w + r*hn.w);
        o.w = (1.f - z)*n + z*h4.w;
    }
    *(float4*)&slots[(size_t)row*DIM + c] = o;
    float sum = o.x + o.y + o.z + o.w;
    float ssq = o.x*o.x + o.y*o.y + o.z*o.z + o.w*o.w;
#pragma unroll
    for (int off = 16; off > 0; off >>= 1) {
        sum += __shfl_xor_sync(0xffffffffu, sum, off);
        ssq += __shfl_xor_sync(0xffffffffu, ssq, off);
    }
    int w = tid >> 5;
    if ((tid & 31) == 0) { r1[w] = sum; r2[w] = ssq; }
    __syncthreads();
    if (tid == 0) {
        float s = r1[0]+r1[1]+r1[2]+r1[3];
        float q = r2[0]+r2[1]+r2[2]+r2[3];
        float mean = s * (1.f/DIM);
        float var  = q * (1.f/DIM) - mean*mean;
        meanf[row] = mean;
        rstdf[row] = rsqrtf(var + 1e-5f);
    }
}

// ---------------- small GEMM: split-K, f32x2 mainloop, precomputed LN stats ----------------
#define GBM 16
#define GBN 64
#define GBK 32
#define GBM2 18
#define GBN2 68

struct GPtrs {
    const float* A; const float* A2; const float* B; const float* B2;
    const float* bias; const float* res;
    float* C; int cstride;
    const float* lnm; const float* lnr; const float* lng; const float* lnb;
};

template<bool TRANSA, bool TRANSB, bool RESID, bool LNA, int KS, bool RELUA>
__global__ __launch_bounds__(128) void gemm16(
    GPtrs p0, GPtrs p1, int lda, int ldb, int ldc, int K)
{
    __shared__ __align__(16) u64   As2[2][GBK*GBM2];
    __shared__ __align__(16) float Bs [2][GBK*GBN2];

    int khalf = blockIdx.z % KS;
    int pair  = blockIdx.z / KS;
    GPtrs P = (pair == 0) ? p0 : p1;
    int Keff = K / KS;

    const float* __restrict__ A  = P.A;
    const float* __restrict__ A2 = P.A2;
    const float* __restrict__ B  = P.B;
    const float* __restrict__ B2v = P.B2;
    const float* __restrict__ lngo = P.lng;
    const float* __restrict__ lnbo = P.lnb;
    if (KS > 1) {
        if (TRANSA) A += (size_t)khalf * Keff * lda;
        else        A += khalf * Keff;
        if (A2) A2 += khalf * Keff;
        if (TRANSB) { B += khalf * Keff; if (B2v) B2v += khalf * Keff; }
        else        { B += (size_t)khalf * Keff * ldb; if (B2v) B2v += (size_t)khalf * Keff * ldb; }
        if (LNA) { lngo += khalf * Keff; lnbo += khalf * Keff; }
    }
    float* C = P.C + (size_t)khalf * P.cstride;

    int tid = threadIdx.x;
    int m0 = blockIdx.x * GBM;
    int n0 = blockIdx.y * GBN;
    int tx = tid & 15;
    int ty = tid >> 4;

    int a_m, a_k;
    if (TRANSA) { a_k = tid >> 2; a_m = (tid & 3) * 4; }
    else        { a_m = tid >> 3; a_k = (tid & 7) * 4; }

    float ln_m = 0.f, ln_r = 1.f;
    if (LNA) { ln_m = P.lnm[m0 + a_m]; ln_r = P.lnr[m0 + a_m]; }

    float4 ar;
    float4 br[4];

    u64 acc00 = 0ull, acc01 = 0ull, acc10 = 0ull, acc11 = 0ull;
    int nT = Keff / GBK;

    #define LOAD_A(t) do { \
        if (TRANSA) ar = *(const float4*)&A[(size_t)((t)*GBK + a_k)*lda + m0 + a_m]; \
        else        ar = *(const float4*)&A[(size_t)(m0 + a_m)*lda + (t)*GBK + a_k]; \
        if (!TRANSA && A2) { \
            float4 a2 = *(const float4*)&A2[(size_t)(m0 + a_m)*lda + (t)*GBK + a_k]; \
            ar.x += a2.x; ar.y += a2.y; ar.z += a2.z; ar.w += a2.w; \
        } \
        if (RELUA) { \
            ar.x = fmaxf(ar.x, 0.f); ar.y = fmaxf(ar.y, 0.f); \
            ar.z = fmaxf(ar.z, 0.f); ar.w = fmaxf(ar.w, 0.f); \
        } \
        if (LNA) { \
            float4 lg = *(const float4*)&lngo[(t)*GBK + a_k]; \
            float4 lb = *(const float4*)&lnbo[(t)*GBK + a_k]; \
            ar.x = (ar.x - ln_m)*ln_r*lg.x + lb.x; \
            ar.y = (ar.y - ln_m)*ln_r*lg.y + lb.y; \
            ar.z = (ar.z - ln_m)*ln_r*lg.z + lb.z; \
            ar.w = (ar.w - ln_m)*ln_r*lg.w + lb.w; \
        } \
    } while (0)
    #define LOAD_B(t) do { \
        _Pragma("unroll") \
        for (int it = 0; it < 4; it++) { \
            int idx = tid + it*128; \
            if (TRANSB) { int n = idx >> 3, kq = (idx & 7)*4; \
                br[it] = *(const float4*)&B[(size_t)(n0+n)*ldb + (t)*GBK + kq]; \
                if (B2v) { float4 e = *(const float4*)&B2v[(size_t)(n0+n)*ldb + (t)*GBK + kq]; \
                    br[it].x+=e.x; br[it].y+=e.y; br[it].z+=e.z; br[it].w+=e.w; } } \
            else { int kk = idx >> 4, nq = (idx & 15)*4; \
                br[it] = *(const float4*)&B[(size_t)((t)*GBK+kk)*ldb + n0 + nq]; \
                if (B2v) { float4 e = *(const float4*)&B2v[(size_t)((t)*GBK+kk)*ldb + n0 + nq]; \
                    br[it].x+=e.x; br[it].y+=e.y; br[it].z+=e.z; br[it].w+=e.w; } } \
        } \
    } while (0)
    #define STORE_AB(buf) do { \
        if (TRANSA) { \
            u64* dst = &As2[buf][a_k*GBM2 + a_m]; \
            dst[0] = pk2(ar.x, ar.x); dst[1] = pk2(ar.y, ar.y); \
            dst[2] = pk2(ar.z, ar.z); dst[3] = pk2(ar.w, ar.w); \
        } else { \
            As2[buf][(a_k+0)*GBM2 + a_m] = pk2(ar.x, ar.x); \
            As2[buf][(a_k+1)*GBM2 + a_m] = pk2(ar.y, ar.y); \
            As2[buf][(a_k+2)*GBM2 + a_m] = pk2(ar.z, ar.z); \
            As2[buf][(a_k+3)*GBM2 + a_m] = pk2(ar.w, ar.w); \
        } \
        _Pragma("unroll") \
        for (int it = 0; it < 4; it++) { \
            int idx = tid + it*128; \
            if (TRANSB) { int n = idx >> 3, kq = (idx & 7)*4; \
                Bs[buf][(kq+0)*GBN2 + n] = br[it].x; \
                Bs[buf][(kq+1)*GBN2 + n] = br[it].y; \
                Bs[buf][(kq+2)*GBN2 + n] = br[it].z; \
                Bs[buf][(kq+3)*GBN2 + n] = br[it].w; \
            } else { int kk = idx >> 4, nq = (idx & 15)*4; \
                *(float4*)&Bs[buf][kk*GBN2 + nq] = br[it]; } \
        } \
    } while (0)

    LOAD_A(0); LOAD_B(0);
    STORE_AB(0);
    __syncthreads();

    for (int t = 0; t < nT; t++) {
        int cur = t & 1;
        bool more = (t+1 < nT);
        if (more) { LOAD_A(t+1); LOAD_B(t+1); }
        ulonglong2 aa = *(const ulonglong2*)&As2[cur][0*GBM2 + ty*2];
        ulonglong2 bb = *(const ulonglong2*)&Bs [cur][0*GBN2 + tx*4];
#pragma unroll
        for (int kk = 0; kk < GBK; kk++) {
            ulonglong2 aan, bbn;
            if (kk + 1 < GBK) {
                aan = *(const ulonglong2*)&As2[cur][(kk+1)*GBM2 + ty*2];
                bbn = *(const ulonglong2*)&Bs [cur][(kk+1)*GBN2 + tx*4];
            }
            acc00 = fma2_(aa.x, bb.x, acc00);
            acc01 = fma2_(aa.x, bb.y, acc01);
            acc10 = fma2_(aa.y, bb.x, acc10);
            acc11 = fma2_(aa.y, bb.y, acc11);
            if (kk + 1 < GBK) { aa = aan; bb = bbn; }
        }
        if (more) {
            __syncthreads();
            STORE_AB((t+1) & 1);
            __syncthreads();
        }
    }
    #undef LOAD_A
    #undef LOAD_B
    #undef STORE_AB

    float c00a,c00b,c01a,c01b,c10a,c10b,c11a,c11b;
    upk2(acc00, c00a, c00b); upk2(acc01, c01a, c01b);
    upk2(acc10, c10a, c10b); upk2(acc11, c11a, c11b);

    float4 bv = make_float4(0.f,0.f,0.f,0.f);
    if (P.bias && khalf == 0) bv = *(const float4*)&P.bias[n0 + tx*4];

    float4 o0 = make_float4(c00a+bv.x, c00b+bv.y, c01a+bv.z, c01b+bv.w);
    float4 o1 = make_float4(c10a+bv.x, c10b+bv.y, c11a+bv.z, c11b+bv.w);
    size_t r0 = (size_t)(m0 + ty*2)*ldc + n0 + tx*4;
    size_t r1 = r0 + ldc;
    if (RESID && khalf == 0) {
        float4 q0 = *(const float4*)&P.res[r0];
        float4 q1 = *(const float4*)&P.res[r1];
        o0.x+=q0.x; o0.y+=q0.y; o0.z+=q0.z; o0.w+=q0.w;
        o1.x+=q1.x; o1.y+=q1.y; o1.z+=q1.z; o1.w+=q1.w;
    }
    *(float4*)&C[r0] = o0;
    *(float4*)&C[r1] = o1;
}

// ---------------- fused attention pass (software-pipelined loads) ----------------
#define ATTN_SMEM (NSLOT*DIM*4 + GTOK*DIM*4 + 2*DIM*4 + GTOK*NSLOT*8 + NSLOT*4 + NSLOT*NSLOT*4 + 64)

__global__ __launch_bounds__(256, 3) void attn_kernel2(
    const float* __restrict__ X,
    const float* __restrict__ g_in, const float* __restrict__ be_in,
    const float* __restrict__ QK, const float* __restrict__ QB,
    float* __restrict__ Upart, float* __restrict__ Spart)
{
    extern __shared__ __align__(16) char smraw[];
    float* qks = (float*)smraw;                       // [8][512]
    float* xs  = qks + NSLOT*DIM;                     // [16][512]
    float* gbs = xs + GTOK*DIM;                       // [2][512]
    u64*   psd = (u64*)(gbs + 2*DIM);                 // [16][8]
    float* qbs = (float*)(psd + GTOK*NSLOT);          // [8]
    float* sred= qbs + NSLOT;                         // [8][8]

    int b   = blockIdx.y;
    int ch  = blockIdx.x;
    int tid = threadIdx.x;
    int w = tid >> 5;
    int l = tid & 31;
    int cb4 = l * 4;

    // stage qk: sum 2 split-K planes
    for (int i = tid*4; i < NSLOT*DIM; i += 1024) {
        float4 a = *(const float4*)&QK[(size_t)b*NSLOT*DIM + i];
        float4 c = *(const float4*)&QK[(size_t)ROWS*DIM + (size_t)b*NSLOT*DIM + i];
        a.x += c.x; a.y += c.y; a.z += c.z; a.w += c.w;
        *(float4*)&qks[i] = a;
    }
    if (tid < 128) {
        *(float4*)&gbs[tid*4]       = *(const float4*)&g_in[tid*4];
        *(float4*)&gbs[DIM + tid*4] = *(const float4*)&be_in[tid*4];
    }
    if (tid < NSLOT) qbs[tid] = QB[b*NSLOT + tid];
    __syncthreads();

    u64 U2[8];
#pragma unroll
    for (int i = 0; i < 8; i++) U2[i] = 0ull;
    float slp = 0.f;

    const float scale = 0.04419417382415922f;   // 512^-0.5
    int tA = 2*w, tB = 2*w + 1;
    int xoff = w*64 + l*2;
    int myslot = (l >> 1) & 7;
    const float* xbase = X + ((size_t)b*NTOK + ch*CTOK)*DIM;

    u64 xvA[8], xvB[8];
    // preload group 0
    {
        const float* xrA = xbase + (size_t)tA*DIM;
        const float* xrB = xrA + DIM;
#pragma unroll
        for (int s = 0; s < 4; s++) {
            ulonglong2 a2 = *(const ulonglong2*)&xrA[s*128 + cb4];
            ulonglong2 b2 = *(const ulonglong2*)&xrB[s*128 + cb4];
            xvA[2*s] = a2.x; xvA[2*s+1] = a2.y;
            xvB[2*s] = b2.x; xvB[2*s+1] = b2.y;
        }
    }

    for (int g = 0; g < CTOK/GTOK; g++) {
        // ---- stats from current registers ----
        u64 sA2 = 0ull, qA2 = 0ull, sB2 = 0ull, qB2 = 0ull;
#pragma unroll
        for (int s = 0; s < 8; s++) {
            sA2 = add2_(sA2, xvA[s]); qA2 = fma2_(xvA[s], xvA[s], qA2);
            sB2 = add2_(sB2, xvB[s]); qB2 = fma2_(xvB[s], xvB[s], qB2);
        }
        float t0, t1;
        upk2(sA2, t0, t1); float sumA = t0 + t1;
        upk2(qA2, t0, t1); float ssqA = t0 + t1;
        upk2(sB2, t0, t1); float sumB = t0 + t1;
        upk2(qB2, t0, t1); float ssqB = t0 + t1;
#pragma unroll
        for (int off = 16; off > 0; off >>= 1) {
            sumA += __shfl_xor_sync(0xffffffffu, sumA, off);
            ssqA += __shfl_xor_sync(0xffffffffu, ssqA, off);
            sumB += __shfl_xor_sync(0xffffffffu, sumB, off);
            ssqB += __shfl_xor_sync(0xffffffffu, ssqB, off);
        }
        float meanA = sumA * (1.f/DIM);
        float invA  = rsqrtf(ssqA*(1.f/DIM) - meanA*meanA + 1e-5f);
        float meanB = sumB * (1.f/DIM);
        float invB  = rsqrtf(ssqB*(1.f/DIM) - meanB*meanB + 1e-5f);
        u64 invA2 = pk2(invA, invA), nmA2 = pk2(-meanA, -meanA);
        u64 invB2 = pk2(invB, invB), nmB2 = pk2(-meanB, -meanB);

        // ---- LN + dots (consumes xv registers) ----
        u64 dA2[8], dB2[8];
#pragma unroll
        for (int i = 0; i < 8; i++) { dA2[i] = 0ull; dB2[i] = 0ull; }
#pragma unroll
        for (int s = 0; s < 4; s++) {
            int c = s*128 + cb4;
            ulonglong2 g2 = *(const ulonglong2*)&gbs[c];
            ulonglong2 b2 = *(const ulonglong2*)&gbs[DIM + c];
            u64 giA0 = mul2_(g2.x, invA2), giA1 = mul2_(g2.y, invA2);
            u64 kA0  = fma2_(nmA2, giA0, b2.x), kA1 = fma2_(nmA2, giA1, b2.y);
            u64 xnA0 = fma2_(xvA[2*s],   giA0, kA0);
            u64 xnA1 = fma2_(xvA[2*s+1], giA1, kA1);
            *(ulonglong2*)&xs[tA*DIM + c] = make_ulonglong2(xnA0, xnA1);
            u64 giB0 = mul2_(g2.x, invB2), giB1 = mul2_(g2.y, invB2);
            u64 kB0  = fma2_(nmB2, giB0, b2.x), kB1 = fma2_(nmB2, giB1, b2.y);
            u64 xnB0 = fma2_(xvB[2*s],   giB0, kB0);
            u64 xnB1 = fma2_(xvB[2*s+1], giB1, kB1);
            *(ulonglong2*)&xs[tB*DIM + c] = make_ulonglong2(xnB0, xnB1);
#pragma unroll
            for (int i = 0; i < 8; i++) {
                ulonglong2 q2 = *(const ulonglong2*)&qks[i*DIM + c];
                dA2[i] = fma2_(q2.x, xnA0, dA2[i]);
                dA2[i] = fma2_(q2.y, xnA1, dA2[i]);
                dB2[i] = fma2_(q2.x, xnB0, dB2[i]);
                dB2[i] = fma2_(q2.y, xnB1, dB2[i]);
            }
        }

        // ---- prefetch next group's tokens (xv registers now dead) ----
        if (g + 1 < CTOK/GTOK) {
            const float* xrA = xbase + (size_t)((g+1)*GTOK + tA)*DIM;
            const float* xrB = xrA + DIM;
#pragma unroll
            for (int s = 0; s < 4; s++) {
                ulonglong2 a2 = *(const ulonglong2*)&xrA[s*128 + cb4];
                ulonglong2 b2 = *(const ulonglong2*)&xrB[s*128 + cb4];
                xvA[2*s] = a2.x; xvA[2*s+1] = a2.y;
                xvB[2*s] = b2.x; xvB[2*s+1] = b2.y;
            }
        }

        float vA[8], vB[8];
#pragma unroll
        for (int i = 0; i < 8; i++) {
            float a0, a1;
            upk2(dA2[i], a0, a1); vA[i] = a0 + a1;
            upk2(dB2[i], a0, a1); vB[i] = a0 + a1;
        }
        // ---- value-compressing butterfly reduce ----
        float v8[8];
#pragma unroll
        for (int i = 0; i < 8; i++) {
            float sa = vA[i] + __shfl_xor_sync(0xffffffffu, vA[i], 16);
            float sb = vB[i] + __shfl_xor_sync(0xffffffffu, vB[i], 16);
            v8[i] = (l < 16) ? sa : sb;
        }
        float v4[4];
#pragma unroll
        for (int i = 0; i < 4; i++) {
            float a = v8[i]   + __shfl_xor_sync(0xffffffffu, v8[i],   8);
            float c = v8[i+4] + __shfl_xor_sync(0xffffffffu, v8[i+4], 8);
            v4[i] = (l & 8) ? c : a;
        }
        float v2[2];
#pragma unroll
        for (int i = 0; i < 2; i++) {
            float a = v4[i]   + __shfl_xor_sync(0xffffffffu, v4[i],   4);
            float c = v4[i+2] + __shfl_xor_sync(0xffffffffu, v4[i+2], 4);
            v2[i] = (l & 4) ? c : a;
        }
        {
            float a = v2[0] + __shfl_xor_sync(0xffffffffu, v2[0], 2);
            float c = v2[1] + __shfl_xor_sync(0xffffffffu, v2[1], 2);
            v2[0] = (l & 2) ? c : a;
        }
        float d = v2[0] + __shfl_xor_sync(0xffffffffu, v2[0], 1);
        d = (d + qbs[myslot]) * scale;
        // distributed softmax over 8 slots within each 16-lane half
        float mx = d;
        mx = fmaxf(mx, __shfl_xor_sync(0xffffffffu, mx, 2));
        mx = fmaxf(mx, __shfl_xor_sync(0xffffffffu, mx, 4));
        mx = fmaxf(mx, __shfl_xor_sync(0xffffffffu, mx, 8));
        float e = __expf(d - mx);
        float se = e;
        se += __shfl_xor_sync(0xffffffffu, se, 2);
        se += __shfl_xor_sync(0xffffffffu, se, 4);
        se += __shfl_xor_sync(0xffffffffu, se, 8);
        float pcur = e / se + 1e-8f;
        slp += pcur;
        if ((l & 1) == 0) {
            int tok = (l < 16) ? tA : tB;
            psd[tok*NSLOT + myslot] = pk2(pcur, pcur);
        }
        __syncthreads();

        // ---- phase 2: warp w accumulates its 64-dim slice for all slots ----
#pragma unroll
        for (int t = 0; t < GTOK; t++) {
            u64 x2 = *(const u64*)&xs[t*DIM + xoff];
            ulonglong2 p01 = *(const ulonglong2*)&psd[t*NSLOT + 0];
            ulonglong2 p23 = *(const ulonglong2*)&psd[t*NSLOT + 2];
            ulonglong2 p45 = *(const ulonglong2*)&psd[t*NSLOT + 4];
            ulonglong2 p67 = *(const ulonglong2*)&psd[t*NSLOT + 6];
            U2[0] = fma2_(p01.x, x2, U2[0]); U2[1] = fma2_(p01.y, x2, U2[1]);
            U2[2] = fma2_(p23.x, x2, U2[2]); U2[3] = fma2_(p23.y, x2, U2[3]);
            U2[4] = fma2_(p45.x, x2, U2[4]); U2[5] = fma2_(p45.y, x2, U2[5]);
            U2[6] = fma2_(p67.x, x2, U2[6]); U2[7] = fma2_(p67.y, x2, U2[7]);
        }
        __syncthreads();
    }

    size_t ub = ((size_t)(b*CH + ch)*NSLOT)*DIM + xoff;
#pragma unroll
    for (int i = 0; i < 8; i++)
        *(u64*)&Upart[ub + (size_t)i*DIM] = U2[i];

    slp += __shfl_xor_sync(0xffffffffu, slp, 16);
    slp += __shfl_xor_sync(0xffffffffu, slp, 1);
    if ((l & 1) == 0 && l < 16) sred[w*8 + (l >> 1)] = slp * 0.5f;
    __syncthreads();
    if (tid < 8) {
        float s = 0.f;
#pragma unroll
        for (int w2 = 0; w2 < 8; w2++) s += sred[w2*8 + tid];
        Spart[(b*CH + ch)*NSLOT + tid] = s;
    }
}

// ---------------- reduce partials ----------------
__global__ void finish_kernel(const float* __restrict__ Upart,
                              const float* __restrict__ Spart,
                              float* __restrict__ Upre)
{
    int bi = blockIdx.x;
    int b = bi >> 3, i = bi & 7;
    int tid = threadIdx.x;          // 128
    __shared__ float ssum_s;
    if (tid < 32) {
        float s = Spart[(b*CH + tid)*NSLOT + i];
#pragma unroll
        for (int off = 16; off > 0; off >>= 1) s += __shfl_xor_sync(0xffffffffu, s, off);
        if (tid == 0) ssum_s = s;
    }
    __syncthreads();
    float rs = 1.f / ssum_s;
    int c = tid * 4;
    float4 acc = make_float4(0.f,0.f,0.f,0.f);
    for (int chn = 0; chn < CH; chn++) {
        float4 v = *(const float4*)&Upart[(((size_t)b*CH + chn)*NSLOT + i)*DIM + c];
        acc.x += v.x; acc.y += v.y; acc.z += v.z; acc.w += v.w;
    }
    acc.x*=rs; acc.y*=rs; acc.z*=rs; acc.w*=rs;
    *(float4*)&Upre[(size_t)bi*DIM + c] = acc;
}

// ---------------- host orchestration ----------------
extern "C" void kernel_launch(void* const* d_in, const int* in_sizes, int n_in,
                              void* d_out, int out_size)
{
    const float* inputs = (const float*)d_in[0];
    const float* noise  = (const float*)d_in[1];
    const float* mu     = (const float*)d_in[2];
    const float* sg     = (const float*)d_in[3];
    const float* Wq = (const float*)d_in[4];
    const float* bq = (const float*)d_in[5];
    const float* Wk = (const float*)d_in[6];
    const float* bk = (const float*)d_in[7];
    const float* Wv = (const float*)d_in[8];
    const float* bv = (const float*)d_in[9];
    const float* W_ih = (const float*)d_in[10];
    const float* b_ih = (const float*)d_in[11];
    const float* W_hh = (const float*)d_in[12];
    const float* b_hh = (const float*)d_in[13];
    const float* W1 = (const float*)d_in[14];
    const float* b1 = (const float*)d_in[15];
    const float* W2 = (const float*)d_in[16];
    const float* b2 = (const float*)d_in[17];
    const float* gin  = (const float*)d_in[18];
    const float* bein = (const float*)d_in[19];
    const float* gsl  = (const float*)d_in[20];
    const float* besl = (const float*)d_in[21];
    const float* gff  = (const float*)d_in[22];
    const float* beff = (const float*)d_in[23];

    float* slots = (float*)d_out;

    void* p;
    cudaGetSymbolAddress(&p, g_qk);    float* qk    = (float*)p;
    cudaGetSymbolAddress(&p, g_qb);    float* qb    = (float*)p;
    cudaGetSymbolAddress(&p, g_Mqk);   float* Mqk   = (float*)p;
    cudaGetSymbolAddress(&p, g_rqk);   float* rqk   = (float*)p;
    cudaGetSymbolAddress(&p, g_u);     float* uvec  = (float*)p;
    cudaGetSymbolAddress(&p, g_c0);    float* c0    = (float*)p;
    cudaGetSymbolAddress(&p, g_scp);   float* scp   = (float*)p;
    cudaGetSymbolAddress(&p, g_mq);    float* mq    = (float*)p;
    cudaGetSymbolAddress(&p, g_rq);    float* rq    = (float*)p;
    cudaGetSymbolAddress(&p, g_mf);    float* mf    = (float*)p;
    cudaGetSymbolAddress(&p, g_rf);    float* rf    = (float*)p;
    cudaGetSymbolAddress(&p, g_upart); float* upart = (float*)p;
    cudaGetSymbolAddress(&p, g_spart); float* spart = (float*)p;
    cudaGetSymbolAddress(&p, g_upre);  float* upre  = (float*)p;
    cudaGetSymbolAddress(&p, g_upd);   float* upd   = (float*)p;
    cudaGetSymbolAddress(&p, g_gx);    float* gx    = (float*)p;
    cudaGetSymbolAddress(&p, g_gh);    float* gh    = (float*)p;
    cudaGetSymbolAddress(&p, g_h1);    float* h1    = (float*)p;

    static bool attr_done = false;
    if (!attr_done) {
        cudaFuncSetAttribute(attn_kernel2, cudaFuncAttributeMaxDynamicSharedMemorySize, ATTN_SMEM);
        attr_done = true;
    }

    GPtrs Z{};

    init_slots_kernel<<<(ROWS*DIM + 255)/256, 256>>>(noise, mu, sg, slots);
    prologue_kernel<<<9, 128>>>(Wq, Wk, bq, bk, gsl, besl, rqk, uvec, scp, c0);

    // Mqk planes = Wq^T @ Wk (split-K=2; qk-GEMM sums the planes on B-load)
    {
        GPtrs a = Z; a.A = Wq; a.B = Wk; a.C = Mqk; a.cstride = DIM*DIM;
        gemm16<true,false,false,false,2,false><<<dim3(DIM/GBM, DIM/GBN, 2), 128>>>(a, a, DIM, DIM, DIM, DIM);
    }

    for (int it = 0; it < 3; it++) {
        stats_q_kernel<<<ROWS/8, 256>>>(slots, gsl, uvec, scp, c0, mq, rq, qb);
        // qk partials = LN(slots) @ (Mqk0+Mqk1) + rqk   (split-K=2)
        {
            GPtrs a = Z; a.A = slots; a.B = Mqk; a.B2 = Mqk + DIM*DIM; a.bias = rqk;
            a.C = qk; a.cstride = ROWS*DIM;
            a.lnm = mq; a.lnr = rq; a.lng = gsl; a.lnb = besl;
            gemm16<false,false,false,true,2,false><<<dim3(ROWS/GBM, DIM/GBN, 2), 128>>>(a, a, DIM, DIM, DIM, DIM);
        }
        attn_kernel2<<<dim3(CH, BATCH), 256, ATTN_SMEM>>>(inputs, gin, bein, qk, qb, upart, spart);
        finish_kernel<<<ROWS, 128>>>(upart, spart, upre);
        // upd partials = Upre @ Wv^T + bv   (split-K=2)
        {
            GPtrs a = Z; a.A = upre; a.B = Wv; a.bias = bv; a.C = upd; a.cstride = ROWS*DIM;
            gemm16<false,true,false,false,2,false><<<dim3(ROWS/GBM, DIM/GBN, 2), 128>>>(a, a, DIM, DIM, DIM, DIM);
        }
        // GRU gates (pairs x split-K=2)
        {
            GPtrs a = Z; a.A = upd;   a.A2 = upd + ROWS*DIM; a.B = W_ih; a.bias = b_ih; a.C = gx; a.cstride = ROWS*3*DIM;
            GPtrs b = Z; b.A = slots; b.A2 = nullptr;        b.B = W_hh; b.bias = b_hh; b.C = gh; b.cstride = ROWS*3*DIM;
            gemm16<false,true,false,false,2,false><<<dim3(ROWS/GBM, (3*DIM)/GBN, 4), 128>>>(a, b, DIM, DIM, 3*DIM, DIM);
        }
        gru_ln_kernel<<<ROWS, 128>>>(gx, gh, slots, mf, rf);
        // h1 partials = LN_ff(slots) @ W1^T + b1   (split-K=2, precomputed stats)
        {
            GPtrs a = Z; a.A = slots; a.B = W1; a.bias = b1; a.C = h1; a.cstride = ROWS*DIM;
            a.lnm = mf; a.lnr = rf; a.lng = gff; a.lnb = beff;
            gemm16<false,true,false,true,2,false><<<dim3(ROWS/GBM, DIM/GBN, 2), 128>>>(a, a, DIM, DIM, DIM, DIM);
        }
        // slots += relu(h10+h11) @ W2^T + b2
        {
            GPtrs a = Z; a.A = h1; a.A2 = h1 + ROWS*DIM; a.B = W2; a.bias = b2; a.res = slots; a.C = slots; a.cstride = 0;
            gemm16<false,true,true,false,1,true><<<dim3(ROWS/GBM, DIM/GBN, 1), 128>>>(a, a, DIM, DIM, DIM, DIM);
        }
    }
}